// round 2
// baseline (speedup 1.0000x reference)
#include <cuda_runtime.h>
#include <cuda_bf16.h>
#include <math.h>

#define BB 64
#define CC 80
#define DE 300
#define DE1 1024
#define JJ 4000
#define SS 100
#define KK 40
#define FDIM 2048

// ---------------- scratch (no allocations allowed) ----------------
__device__ float g_feat[BB * FDIM];        // [64, 2048]
__device__ float g_b1[DE1 * CC];           // [1024, 80]
__device__ float g_b2[DE1 * CC];           // [1024, 80]
__device__ float g_Awave[CC * CC];         // A + I
__device__ float g_Ahat[CC * CC];
__device__ float g_dvec[CC];
__device__ float g_t1[CC * DE1];           // inp @ Wg1
__device__ float g_h[CC * DE1];            // leaky(Ahat @ t1)
__device__ float g_y[CC * FDIM];           // h @ Wg2
__device__ float g_x[CC * FDIM];           // Ahat @ y
__device__ float g_img[BB * JJ];           // [64, 4000]
__device__ float g_cls[CC * JJ];           // [80, 4000]
__device__ float g_pooled[BB * CC * KK];   // [64, 80*40]

// ---------------- kernels ----------------

// MaxPool2d(14,14): one warp per (b, ch)
__global__ void k_maxpool(const float* __restrict__ f) {
    int warp = (blockIdx.x * blockDim.x + threadIdx.x) >> 5;
    int lane = threadIdx.x & 31;
    if (warp >= BB * FDIM) return;
    const float* p = f + (size_t)warp * 196;
    float m = -INFINITY;
    for (int i = lane; i < 196; i += 32) m = fmaxf(m, p[i]);
    #pragma unroll
    for (int o = 16; o; o >>= 1) m = fmaxf(m, __shfl_xor_sync(0xffffffffu, m, o));
    if (lane == 0) g_feat[warp] = m;
}

// b1 = sigmoid(Wb1 @ X + bb1), b2 likewise. X[d][c] = inp_flat[d*80+c]
__global__ void k_b1b2(const float* __restrict__ Wb1, const float* __restrict__ bb1,
                       const float* __restrict__ Wb2, const float* __restrict__ bb2,
                       const float* __restrict__ inp) {
    int idx = blockIdx.x * blockDim.x + threadIdx.x;
    if (idx >= 2 * DE1 * CC) return;
    int which = idx / (DE1 * CC);
    int r = idx % (DE1 * CC);
    int i = r / CC, c = r % CC;
    const float* W = which ? Wb2 : Wb1;
    const float* bv = which ? bb2 : bb1;
    float s = bv[i];
    #pragma unroll 4
    for (int d = 0; d < DE; d++) s = fmaf(W[i * DE + d], inp[d * CC + c], s);
    s = 1.0f / (1.0f + expf(-s));
    (which ? g_b2 : g_b1)[r] = s;
}

// A_wave = (b1.T @ b2)/C + I
__global__ void k_awave() {
    int idx = blockIdx.x * blockDim.x + threadIdx.x;
    if (idx >= CC * CC) return;
    int i = idx / CC, j = idx % CC;
    float s = 0.f;
    #pragma unroll 4
    for (int k = 0; k < DE1; k++) s = fmaf(g_b1[k * CC + i], g_b2[k * CC + j], s);
    g_Awave[idx] = s * (1.0f / CC) + (i == j ? 1.0f : 0.0f);
}

// d = rowsum(A_wave)^-0.5, non-finite -> 0
__global__ void k_dvec() {
    int i = threadIdx.x;
    if (i >= CC) return;
    float s = 0.f;
    for (int j = 0; j < CC; j++) s += g_Awave[i * CC + j];
    float d = powf(s, -0.5f);
    if (!isfinite(d)) d = 0.f;
    g_dvec[i] = d;
}

__global__ void k_ahat() {
    int idx = blockIdx.x * blockDim.x + threadIdx.x;
    if (idx >= CC * CC) return;
    int i = idx / CC, j = idx % CC;
    g_Ahat[idx] = g_dvec[i] * g_Awave[idx] * g_dvec[j];
}

// L_A_loss = sum |A_hat - I| : single-block deterministic reduction
__global__ void k_loss(float* __restrict__ out_loss) {
    __shared__ float red[256];
    int t = threadIdx.x;
    float s = 0.f;
    for (int idx = t; idx < CC * CC; idx += 256) {
        int i = idx / CC, j = idx % CC;
        s += fabsf(g_Ahat[idx] - (i == j ? 1.0f : 0.0f));
    }
    red[t] = s;
    __syncthreads();
    for (int o = 128; o; o >>= 1) {
        if (t < o) red[t] += red[t + o];
        __syncthreads();
    }
    if (t == 0) *out_loss = red[0];
}

// h = leaky_relu(Ahat @ t1, 0.2)
__global__ void k_gcn1() {
    int idx = blockIdx.x * blockDim.x + threadIdx.x;
    if (idx >= CC * DE1) return;
    int i = idx / DE1, j = idx % DE1;
    float s = 0.f;
    #pragma unroll 4
    for (int k = 0; k < CC; k++) s = fmaf(g_Ahat[i * CC + k], g_t1[k * DE1 + j], s);
    g_h[idx] = s > 0.f ? s : 0.2f * s;
}

// x = Ahat @ y
__global__ void k_gcn2() {
    int idx = blockIdx.x * blockDim.x + threadIdx.x;
    if (idx >= CC * FDIM) return;
    int i = idx / FDIM, j = idx % FDIM;
    float s = 0.f;
    #pragma unroll 4
    for (int k = 0; k < CC; k++) s = fmaf(g_Ahat[i * CC + k], g_y[k * FDIM + j], s);
    g_x[idx] = s;
}

// pooled[b][c][k] = sum_s img[b, k*100+s] * cls[c, k*100+s]
__global__ void k_pooled() {
    int idx = blockIdx.x * blockDim.x + threadIdx.x;
    if (idx >= BB * CC * KK) return;
    int b = idx / (CC * KK);
    int r = idx % (CC * KK);
    int c = r / KK, k = r % KK;
    const float* ip = g_img + (size_t)b * JJ + k * SS;
    const float* cp = g_cls + (size_t)c * JJ + k * SS;
    float s = 0.f;
    #pragma unroll 4
    for (int t = 0; t < SS; t++) s = fmaf(ip[t], cp[t], s);
    g_pooled[idx] = s;
}

// Register-tiled GEMM: C[M,N] = A[M,K] @ op(B) (+bias)
// TRANSB=true : B is [N,K] row-major (C = A @ B^T)
// TRANSB=false: B is [K,N] row-major (C = A @ B)
// BM=32, BN=64, BK=16, 256 threads, 2x4 outputs/thread
template <bool TRANSB>
__global__ void gemm_tile(const float* __restrict__ A, const float* __restrict__ Bm,
                          const float* __restrict__ bias, float* __restrict__ Cm,
                          int M, int N, int K) {
    __shared__ float As[32][16];
    __shared__ float Bs[64][17];
    int tid = threadIdx.x;
    int tx = tid & 15;   // 0..15 -> 4 cols each
    int ty = tid >> 4;   // 0..15 -> 2 rows each
    int m0 = blockIdx.y * 32;
    int n0 = blockIdx.x * 64;
    float acc00 = 0, acc01 = 0, acc02 = 0, acc03 = 0;
    float acc10 = 0, acc11 = 0, acc12 = 0, acc13 = 0;

    for (int k0 = 0; k0 < K; k0 += 16) {
        // load A tile: 512 elems, 2/thread, coalesced rows of 16
        #pragma unroll
        for (int p = 0; p < 2; p++) {
            int idx = tid + p * 256;
            int m = idx >> 4, kk = idx & 15;
            int gm = m0 + m, gk = k0 + kk;
            float v = (gm < M && gk < K) ? A[(size_t)gm * K + gk] : 0.f;
            As[m][kk] = v;
        }
        // load B tile: 1024 elems, 4/thread
        #pragma unroll
        for (int p = 0; p < 4; p++) {
            int idx = tid + p * 256;
            if (TRANSB) {
                int n = idx >> 4, kk = idx & 15;
                int gn = n0 + n, gk = k0 + kk;
                float v = (gn < N && gk < K) ? Bm[(size_t)gn * K + gk] : 0.f;
                Bs[n][kk] = v;
            } else {
                int n = idx & 63, kk = idx >> 6;
                int gn = n0 + n, gk = k0 + kk;
                float v = (gn < N && gk < K) ? Bm[(size_t)gk * N + gn] : 0.f;
                Bs[n][kk] = v;
            }
        }
        __syncthreads();
        #pragma unroll
        for (int kk = 0; kk < 16; kk++) {
            float a0 = As[ty * 2 + 0][kk];
            float a1 = As[ty * 2 + 1][kk];
            float b0 = Bs[tx * 4 + 0][kk];
            float b1 = Bs[tx * 4 + 1][kk];
            float b2 = Bs[tx * 4 + 2][kk];
            float b3 = Bs[tx * 4 + 3][kk];
            acc00 = fmaf(a0, b0, acc00); acc01 = fmaf(a0, b1, acc01);
            acc02 = fmaf(a0, b2, acc02); acc03 = fmaf(a0, b3, acc03);
            acc10 = fmaf(a1, b0, acc10); acc11 = fmaf(a1, b1, acc11);
            acc12 = fmaf(a1, b2, acc12); acc13 = fmaf(a1, b3, acc13);
        }
        __syncthreads();
    }

    int row0 = m0 + ty * 2, row1 = row0 + 1;
    int col = n0 + tx * 4;
    float bv0 = 0, bv1 = 0, bv2 = 0, bv3 = 0;
    if (bias) {
        if (col + 0 < N) bv0 = bias[col + 0];
        if (col + 1 < N) bv1 = bias[col + 1];
        if (col + 2 < N) bv2 = bias[col + 2];
        if (col + 3 < N) bv3 = bias[col + 3];
    }
    if (row0 < M) {
        if (col + 0 < N) Cm[(size_t)row0 * N + col + 0] = acc00 + bv0;
        if (col + 1 < N) Cm[(size_t)row0 * N + col + 1] = acc01 + bv1;
        if (col + 2 < N) Cm[(size_t)row0 * N + col + 2] = acc02 + bv2;
        if (col + 3 < N) Cm[(size_t)row0 * N + col + 3] = acc03 + bv3;
    }
    if (row1 < M) {
        if (col + 0 < N) Cm[(size_t)row1 * N + col + 0] = acc10 + bv0;
        if (col + 1 < N) Cm[(size_t)row1 * N + col + 1] = acc11 + bv1;
        if (col + 2 < N) Cm[(size_t)row1 * N + col + 2] = acc12 + bv2;
        if (col + 3 < N) Cm[(size_t)row1 * N + col + 3] = acc13 + bv3;
    }
}

// ---------------- launcher ----------------

static inline float* symaddr(const void* sym) {
    void* p = nullptr;
    cudaGetSymbolAddress(&p, sym);
    return (float*)p;
}

extern "C" void kernel_launch(void* const* d_in, const int* in_sizes, int n_in,
                              void* d_out, int out_size) {
    const float* feature = (const float*)d_in[0];
    const float* inp     = (const float*)d_in[1];
    const float* Wb1     = (const float*)d_in[2];
    const float* bb1     = (const float*)d_in[3];
    const float* Wb2     = (const float*)d_in[4];
    const float* bb2     = (const float*)d_in[5];
    const float* Wg1     = (const float*)d_in[6];
    const float* Wg2     = (const float*)d_in[7];
    const float* Wimg    = (const float*)d_in[8];
    const float* bimg    = (const float*)d_in[9];
    const float* Wcls    = (const float*)d_in[10];
    const float* bcls    = (const float*)d_in[11];
    const float* Wml     = (const float*)d_in[12];
    const float* bml     = (const float*)d_in[13];
    float* out = (float*)d_out;

    float* p_feat   = symaddr(g_feat);
    float* p_t1     = symaddr(g_t1);
    float* p_h      = symaddr(g_h);
    float* p_y      = symaddr(g_y);
    float* p_x      = symaddr(g_x);
    float* p_img    = symaddr(g_img);
    float* p_cls    = symaddr(g_cls);
    float* p_pooled = symaddr(g_pooled);

    // 1) maxpool: warp per (b,ch)
    {
        int warps = BB * FDIM;
        int blocks = (warps * 32 + 255) / 256;
        k_maxpool<<<blocks, 256>>>(feature);
    }
    // 2) sigmoid branches
    k_b1b2<<<(2 * DE1 * CC + 255) / 256, 256>>>(Wb1, bb1, Wb2, bb2, inp);
    // 3) A_wave, d, A_hat, loss
    k_awave<<<(CC * CC + 255) / 256, 256>>>();
    k_dvec<<<1, 128>>>();
    k_ahat<<<(CC * CC + 255) / 256, 256>>>();
    if (out_size > BB * CC) k_loss<<<1, 256>>>(out + BB * CC);
    // 4) GCN: t1 = inp @ Wg1   [80,300]x[300,1024]
    gemm_tile<false><<<dim3((DE1 + 63) / 64, (CC + 31) / 32), 256>>>(
        inp, Wg1, nullptr, p_t1, CC, DE1, DE);
    // 5) h = leaky(Ahat @ t1)
    k_gcn1<<<(CC * DE1 + 255) / 256, 256>>>();
    // 6) y = h @ Wg2   [80,1024]x[1024,2048]
    gemm_tile<false><<<dim3((FDIM + 63) / 64, (CC + 31) / 32), 256>>>(
        p_h, Wg2, nullptr, p_y, CC, FDIM, DE1);
    // 7) x = Ahat @ y
    k_gcn2<<<(CC * FDIM + 255) / 256, 256>>>();
    // 8) img = feat @ Wimg^T + bimg   [64,2048]x[4000,2048]^T
    gemm_tile<true><<<dim3((JJ + 63) / 64, (BB + 31) / 32), 256>>>(
        p_feat, Wimg, bimg, p_img, BB, JJ, FDIM);
    // 9) cls = x @ Wcls^T + bcls   [80,2048]x[4000,2048]^T
    gemm_tile<true><<<dim3((JJ + 63) / 64, (CC + 31) / 32), 256>>>(
        p_x, Wcls, bcls, p_cls, CC, JJ, FDIM);
    // 10) pooled einsum
    k_pooled<<<(BB * CC * KK + 255) / 256, 256>>>();
    // 11) out = pooled @ Wml^T + bml   [64,3200]x[80,3200]^T
    gemm_tile<true><<<dim3((CC + 63) / 64, (BB + 31) / 32), 256>>>(
        p_pooled, Wml, bml, out, BB, CC, CC * KK);
}

// round 3
// speedup vs baseline: 2.8486x; 2.8486x over previous
#include <cuda_runtime.h>
#include <cuda_bf16.h>
#include <math.h>

#define BB 64
#define CC 80
#define DE 300
#define DE1 1024
#define JJ 4000
#define SS 100
#define KK 40
#define FDIM 2048

typedef unsigned long long ull;

// ---------------- scratch (no allocations allowed) ----------------
__device__ float g_feat[BB * FDIM];          // [64, 2048]
__device__ float g_b1t[CC * DE1];            // b1 transposed: [80][1024]
__device__ float g_b2t[CC * DE1];            // b2 transposed: [80][1024]
__device__ float g_Awave[CC * CC];
__device__ float g_Ahat[CC * CC];
__device__ float g_t1[CC * DE1];             // inp @ Wg1
__device__ float g_h[CC * DE1];              // leaky(Ahat @ t1)
__device__ float g_y[CC * FDIM];             // h @ Wg2
__device__ float g_x[CC * FDIM];             // Ahat @ y
__device__ float g_img[BB * JJ];             // [64, 4000]
__device__ float g_cls[CC * JJ];             // [80, 4000]
__device__ float g_pooled[BB * CC * KK];     // [64, 3200]
__device__ float g_slab[4 * BB * JJ];        // split-K partials (4.1 MB max)

// ---------------- f32x2 helpers ----------------
__device__ __forceinline__ ull pack2(float lo, float hi) {
    ull r; asm("mov.b64 %0, {%1,%2};" : "=l"(r) : "f"(lo), "f"(hi)); return r;
}
__device__ __forceinline__ void unpack2(ull v, float& lo, float& hi) {
    asm("mov.b64 {%0,%1}, %2;" : "=f"(lo), "=f"(hi) : "l"(v));
}
__device__ __forceinline__ ull ffma2(ull a, ull b, ull c) {
    ull d; asm("fma.rn.f32x2 %0, %1, %2, %3;" : "=l"(d) : "l"(a), "l"(b), "l"(c)); return d;
}

// ---------------- kernels ----------------

// MaxPool2d(14,14): one warp per (b, ch)
__global__ void k_maxpool(const float* __restrict__ f) {
    int warp = (blockIdx.x * blockDim.x + threadIdx.x) >> 5;
    int lane = threadIdx.x & 31;
    if (warp >= BB * FDIM) return;
    const float* p = f + (size_t)warp * 196;
    float m = -INFINITY;
    #pragma unroll
    for (int i = 0; i < 7; i++) {
        int idx = lane + i * 32;
        if (idx < 196) m = fmaxf(m, p[idx]);
    }
    #pragma unroll
    for (int o = 16; o; o >>= 1) m = fmaxf(m, __shfl_xor_sync(0xffffffffu, m, o));
    if (lane == 0) g_feat[warp] = m;
}

// b1t[c][i] = sigmoid(Wb1[i,:] . X[:,c] + bb1[i]), likewise b2t
__global__ void k_b1b2(const float* __restrict__ Wb1, const float* __restrict__ bb1,
                       const float* __restrict__ Wb2, const float* __restrict__ bb2,
                       const float* __restrict__ inp) {
    int idx = blockIdx.x * blockDim.x + threadIdx.x;
    if (idx >= 2 * DE1 * CC) return;
    int which = idx / (DE1 * CC);
    int r = idx % (DE1 * CC);
    int i = r / CC, c = r % CC;
    const float* W = which ? Wb2 : Wb1;
    const float* bv = which ? bb2 : bb1;
    float s = bv[i];
    #pragma unroll 4
    for (int d = 0; d < DE; d++) s = fmaf(W[i * DE + d], inp[d * CC + c], s);
    s = 1.0f / (1.0f + expf(-s));
    (which ? g_b2t : g_b1t)[c * DE1 + i] = s;
}

// A_wave[i][j] = (b1t[i] . b2t[j]) / C + (i==j) ; warp per output
__global__ void k_awave() {
    int w = (blockIdx.x * blockDim.x + threadIdx.x) >> 5;
    int lane = threadIdx.x & 31;
    if (w >= CC * CC) return;
    int i = w / CC, j = w % CC;
    const float* p1 = g_b1t + (size_t)i * DE1;
    const float* p2 = g_b2t + (size_t)j * DE1;
    float s = 0.f;
    #pragma unroll 8
    for (int k = lane; k < DE1; k += 32) s = fmaf(p1[k], p2[k], s);
    #pragma unroll
    for (int o = 16; o; o >>= 1) s += __shfl_xor_sync(0xffffffffu, s, o);
    if (lane == 0) g_Awave[w] = s * (1.0f / CC) + (i == j ? 1.0f : 0.0f);
}

// fused: dvec = rowsum^-0.5 (nonfinite->0), Ahat, L_A_loss ; single block 1024 thr
__global__ void k_norm(float* __restrict__ out_loss) {
    __shared__ float red[CC][8];
    __shared__ float dsh[CC];
    __shared__ float lred[1024];
    int t = threadIdx.x;
    if (t < CC * 8) {
        int i = t >> 3, p = t & 7;
        float s = 0.f;
        #pragma unroll
        for (int j = p * 10; j < p * 10 + 10; j++) s += g_Awave[i * CC + j];
        red[i][p] = s;
    }
    __syncthreads();
    if (t < CC) {
        float s = 0.f;
        #pragma unroll
        for (int p = 0; p < 8; p++) s += red[t][p];
        float d = rsqrtf(s);
        if (!isfinite(d)) d = 0.f;
        dsh[t] = d;
    }
    __syncthreads();
    float ls = 0.f;
    for (int idx = t; idx < CC * CC; idx += 1024) {
        int i = idx / CC, j = idx % CC;
        float v = dsh[i] * g_Awave[idx] * dsh[j];
        g_Ahat[idx] = v;
        ls += fabsf(v - (i == j ? 1.0f : 0.0f));
    }
    lred[t] = ls;
    __syncthreads();
    for (int o = 512; o; o >>= 1) {
        if (t < o) lred[t] += lred[t + o];
        __syncthreads();
    }
    if (t == 0 && out_loss) *out_loss = lred[0];
}

// h = leaky_relu(Ahat @ t1, 0.2)
__global__ void k_gcn1() {
    int idx = blockIdx.x * blockDim.x + threadIdx.x;
    if (idx >= CC * DE1) return;
    int i = idx / DE1, j = idx % DE1;
    float s = 0.f;
    #pragma unroll 8
    for (int k = 0; k < CC; k++) s = fmaf(g_Ahat[i * CC + k], g_t1[k * DE1 + j], s);
    g_h[idx] = s > 0.f ? s : 0.2f * s;
}

// x = Ahat @ y
__global__ void k_gcn2() {
    int idx = blockIdx.x * blockDim.x + threadIdx.x;
    if (idx >= CC * FDIM) return;
    int i = idx / FDIM, j = idx % FDIM;
    float s = 0.f;
    #pragma unroll 8
    for (int k = 0; k < CC; k++) s = fmaf(g_Ahat[i * CC + k], g_y[k * FDIM + j], s);
    g_x[idx] = s;
}

// ---------------- FFMA2 split-K GEMM: BM=64 BN=64 BK=16, 256 thr, 4x4/thread ----------------
// C = A[M,K] @ op(B) ; TRANSB: B[N,K] (A@B^T) else B[K,N] (A@B)
// writes partial to slab[z*M*N + ...], k-range [z*kchunk, min(K,(z+1)*kchunk))
template <bool TRANSB>
__global__ void gemm_ffma2(const float* __restrict__ A, const float* __restrict__ B,
                           float* __restrict__ slab, int M, int N, int K, int kchunk) {
    __shared__ float As[16][68];   // [kk][m], 68 stride keeps 16B align + low conflicts
    __shared__ float Bs[16][68];   // [kk][n]
    int tid = threadIdx.x;
    int tx = tid & 15, ty = tid >> 4;
    int m0 = blockIdx.y * 64, n0 = blockIdx.x * 64;
    int z = blockIdx.z;
    int kbeg = z * kchunk;
    int kend = min(K, kbeg + kchunk);

    ull acc[4][2] = {{0ull,0ull},{0ull,0ull},{0ull,0ull},{0ull,0ull}};

    for (int k0 = kbeg; k0 < kend; k0 += 16) {
        int kk_l = tid & 15;
        int gk_l = k0 + kk_l;
        #pragma unroll
        for (int p = 0; p < 4; p++) {
            int m = (tid >> 4) + p * 16;
            int gm = m0 + m;
            float v = (gm < M && gk_l < kend) ? A[(size_t)gm * K + gk_l] : 0.f;
            As[kk_l][m] = v;
        }
        #pragma unroll
        for (int p = 0; p < 4; p++) {
            if (TRANSB) {
                int n = (tid >> 4) + p * 16;
                int gn = n0 + n;
                float v = (gn < N && gk_l < kend) ? B[(size_t)gn * K + gk_l] : 0.f;
                Bs[kk_l][n] = v;
            } else {
                int kk = (tid >> 6) + p * 4, n = tid & 63;
                int gk = k0 + kk, gn = n0 + n;
                float v = (gn < N && gk < kend) ? B[(size_t)gk * N + gn] : 0.f;
                Bs[kk][n] = v;
            }
        }
        __syncthreads();
        #pragma unroll
        for (int kk = 0; kk < 16; kk++) {
            float4 av = *(const float4*)&As[kk][ty * 4];
            float4 bv = *(const float4*)&Bs[kk][tx * 4];
            ull bb0 = pack2(bv.x, bv.y);
            ull bb1 = pack2(bv.z, bv.w);
            ull a0 = pack2(av.x, av.x);
            ull a1 = pack2(av.y, av.y);
            ull a2 = pack2(av.z, av.z);
            ull a3 = pack2(av.w, av.w);
            acc[0][0] = ffma2(a0, bb0, acc[0][0]); acc[0][1] = ffma2(a0, bb1, acc[0][1]);
            acc[1][0] = ffma2(a1, bb0, acc[1][0]); acc[1][1] = ffma2(a1, bb1, acc[1][1]);
            acc[2][0] = ffma2(a2, bb0, acc[2][0]); acc[2][1] = ffma2(a2, bb1, acc[2][1]);
            acc[3][0] = ffma2(a3, bb0, acc[3][0]); acc[3][1] = ffma2(a3, bb1, acc[3][1]);
        }
        __syncthreads();
    }

    float* Cz = slab + (size_t)z * M * N;
    #pragma unroll
    for (int r = 0; r < 4; r++) {
        int gm = m0 + ty * 4 + r;
        if (gm >= M) continue;
        float v0, v1, v2, v3;
        unpack2(acc[r][0], v0, v1);
        unpack2(acc[r][1], v2, v3);
        int gn = n0 + tx * 4;
        size_t base = (size_t)gm * N + gn;
        if (gn + 0 < N) Cz[base + 0] = v0;
        if (gn + 1 < N) Cz[base + 1] = v1;
        if (gn + 2 < N) Cz[base + 2] = v2;
        if (gn + 3 < N) Cz[base + 3] = v3;
    }
}

// sum split-K slabs + optional bias -> dst
__global__ void k_reduce(const float* __restrict__ slab, const float* __restrict__ bias,
                         float* __restrict__ dst, int M, int N, int splits) {
    int idx = blockIdx.x * blockDim.x + threadIdx.x;
    if (idx >= M * N) return;
    float s = 0.f;
    for (int z = 0; z < splits; z++) s += slab[(size_t)z * M * N + idx];
    if (bias) s += bias[idx % N];
    dst[idx] = s;
}

// pooled[b][c][k] = sum_s img[b][k*100+s] * cls[c][k*100+s]
// block = (k, b-half of 32). smem-staged, odd stride (conflict-free)
__global__ void k_pooled() {
    __shared__ float simg[32][101];
    __shared__ float scls[CC][101];
    int k = blockIdx.x % KK;
    int b0 = (blockIdx.x / KK) * 32;
    int tid = threadIdx.x;
    for (int idx = tid; idx < 32 * SS; idx += 256) {
        int r = idx / SS, s = idx % SS;
        simg[r][s] = g_img[(size_t)(b0 + r) * JJ + k * SS + s];
    }
    for (int idx = tid; idx < CC * SS; idx += 256) {
        int c = idx / SS, s = idx % SS;
        scls[c][s] = g_cls[(size_t)c * JJ + k * SS + s];
    }
    __syncthreads();
    for (int o = tid; o < 32 * CC; o += 256) {
        int lb = o / CC, c = o % CC;
        float acc = 0.f;
        #pragma unroll 4
        for (int s = 0; s < SS; s++) acc = fmaf(simg[lb][s], scls[c][s], acc);
        g_pooled[(size_t)(b0 + lb) * (CC * KK) + c * KK + k] = acc;
    }
}

// out = pooled @ Wml^T + bml  [64,3200]x[80,3200]^T : warp per output
__global__ void k_outgemm(const float* __restrict__ Wml, const float* __restrict__ bml,
                          float* __restrict__ out) {
    int w = (blockIdx.x * blockDim.x + threadIdx.x) >> 5;
    int lane = threadIdx.x & 31;
    if (w >= BB * CC) return;
    int b = w / CC, c = w % CC;
    const float* pp = g_pooled + (size_t)b * (CC * KK);
    const float* wp = Wml + (size_t)c * (CC * KK);
    float s = 0.f;
    #pragma unroll 8
    for (int t = lane; t < CC * KK; t += 32) s = fmaf(pp[t], wp[t], s);
    #pragma unroll
    for (int o = 16; o; o >>= 1) s += __shfl_xor_sync(0xffffffffu, s, o);
    if (lane == 0) out[w] = s + bml[c];
}

// ---------------- launcher ----------------

static inline float* symaddr(const void* sym) {
    void* p = nullptr;
    cudaGetSymbolAddress(&p, sym);
    return (float*)p;
}

extern "C" void kernel_launch(void* const* d_in, const int* in_sizes, int n_in,
                              void* d_out, int out_size) {
    const float* feature = (const float*)d_in[0];
    const float* inp     = (const float*)d_in[1];
    const float* Wb1     = (const float*)d_in[2];
    const float* bb1     = (const float*)d_in[3];
    const float* Wb2     = (const float*)d_in[4];
    const float* bb2     = (const float*)d_in[5];
    const float* Wg1     = (const float*)d_in[6];
    const float* Wg2     = (const float*)d_in[7];
    const float* Wimg    = (const float*)d_in[8];
    const float* bimg    = (const float*)d_in[9];
    const float* Wcls    = (const float*)d_in[10];
    const float* bcls    = (const float*)d_in[11];
    const float* Wml     = (const float*)d_in[12];
    const float* bml     = (const float*)d_in[13];
    float* out = (float*)d_out;

    float* p_t1   = symaddr(g_t1);
    float* p_y    = symaddr(g_y);
    float* p_img  = symaddr(g_img);
    float* p_cls  = symaddr(g_cls);
    float* p_h    = symaddr(g_h);
    float* p_x    = symaddr(g_x);
    float* p_feat = symaddr(g_feat);
    float* p_slab = symaddr(g_slab);

    // 1) maxpool
    k_maxpool<<<(BB * FDIM * 32 + 255) / 256, 256>>>(feature);
    // 2) sigmoid branches (transposed outputs)
    k_b1b2<<<(2 * DE1 * CC + 255) / 256, 256>>>(Wb1, bb1, Wb2, bb2, inp);
    // 3) A_wave (warp-dot) + fused normalization & loss
    k_awave<<<(CC * CC * 32 + 255) / 256, 256>>>();
    k_norm<<<1, 1024>>>(out_size > BB * CC ? out + BB * CC : nullptr);
    // 4) t1 = inp @ Wg1  [80,300]x[300,1024]
    gemm_ffma2<false><<<dim3(16, 2, 1), 256>>>(inp, Wg1, p_slab, CC, DE1, DE, DE);
    k_reduce<<<(CC * DE1 + 255) / 256, 256>>>(p_slab, nullptr, p_t1, CC, DE1, 1);
    // 5) h = leaky(Ahat @ t1)
    k_gcn1<<<(CC * DE1 + 255) / 256, 256>>>();
    // 6) y = h @ Wg2  [80,1024]x[1024,2048], split-K 2
    gemm_ffma2<false><<<dim3(32, 2, 2), 256>>>(p_h, Wg2, p_slab, CC, FDIM, DE1, 512);
    k_reduce<<<(CC * FDIM + 255) / 256, 256>>>(p_slab, nullptr, p_y, CC, FDIM, 2);
    // 7) x = Ahat @ y
    k_gcn2<<<(CC * FDIM + 255) / 256, 256>>>();
    // 8) img = feat @ Wimg^T + bimg  [64,4000,2048], split-K 4
    gemm_ffma2<true><<<dim3(63, 1, 4), 256>>>(p_feat, Wimg, p_slab, BB, JJ, FDIM, 512);
    k_reduce<<<(BB * JJ + 255) / 256, 256>>>(p_slab, bimg, p_img, BB, JJ, 4);
    // 9) cls = x @ Wcls^T + bcls  [80,4000,2048], split-K 2
    gemm_ffma2<true><<<dim3(63, 2, 2), 256>>>(p_x, Wcls, p_slab, CC, JJ, FDIM, 1024);
    k_reduce<<<(CC * JJ + 255) / 256, 256>>>(p_slab, bcls, p_cls, CC, JJ, 2);
    // 10) pooled einsum (smem-staged)
    k_pooled<<<KK * 2, 256>>>();
    // 11) out = pooled @ Wml^T + bml (warp-dot)
    k_outgemm<<<(BB * CC * 32 + 255) / 256, 256>>>(Wml, bml, out);
}